// round 2
// baseline (speedup 1.0000x reference)
#include <cuda_runtime.h>
#include <cstdint>

#define NE 100000
#define NA 10000

// Scratch (static device globals — no allocation)
static __device__ float g_uncf[NA * 40 * 32];   // uncoupled features per atom
static __device__ float g_pool[NA * 40 * 32];   // pooled messages per atom

__device__ __forceinline__ int dd2g(int dd) { return (dd == 0) ? 0 : (dd < 4) ? 1 : (dd < 13) ? 2 : 3; }
__device__ __forceinline__ int goff_u(int g) { return (g == 0) ? 0 : (g == 1) ? 1 : (g == 2) ? 13 : 94; }   // U concat offsets
__device__ __forceinline__ int goff_d(int g) { return (g == 0) ? 0 : (g == 1) ? 1 : (g == 2) ? 4 : 13; }    // dd offsets
__device__ __forceinline__ int pow3g(int g)  { return (g == 0) ? 1 : (g == 1) ? 3 : (g == 2) ? 9 : 27; }
__device__ __forceinline__ int foff(int lp)  { return (lp == 0) ? 0 : (lp == 1) ? 128 : (lp == 2) ? 416 : 736; }
__device__ __forceinline__ int klen(int lp)  { return 32 * (4 - lp); }

// ---------------------------------------------------------------------------
// K1: per-atom uncoupled features  g_uncf[n][dd][k]
//     unc_f[g][d][k] = sum_{lp<=g, mm} U_g[d][lp^2+mm] * feat_lp[n][mm][32*(3-g)+k]
// ---------------------------------------------------------------------------
__global__ void __launch_bounds__(256) k_uncf(
    const float* __restrict__ f0, const float* __restrict__ f1,
    const float* __restrict__ f2, const float* __restrict__ f3,
    const float* __restrict__ U0, const float* __restrict__ U1,
    const float* __restrict__ U2, const float* __restrict__ U3)
{
    __shared__ float fs[960];
    __shared__ float Us[526];
    const int n = blockIdx.x, t = threadIdx.x;
    for (int i = t; i < 128; i += 256) fs[i]       = f0[n * 128 + i];
    for (int i = t; i < 288; i += 256) fs[128 + i] = f1[n * 288 + i];
    for (int i = t; i < 320; i += 256) fs[416 + i] = f2[n * 320 + i];
    for (int i = t; i < 224; i += 256) fs[736 + i] = f3[n * 224 + i];
    if (t == 0) Us[0] = U0[0];
    for (int i = t; i < 12;  i += 256) Us[1  + i] = U1[i];
    for (int i = t; i < 81;  i += 256) Us[13 + i] = U2[i];
    for (int i = t; i < 432; i += 256) Us[94 + i] = U3[i];
    __syncthreads();

    const int lane = t & 31, row = t >> 5;
    float* outp = g_uncf + (size_t)n * 1280;
    #pragma unroll
    for (int i = 0; i < 5; i++) {
        int dd = row + 8 * i;                 // warp-uniform
        int g  = dd2g(dd);
        int d  = dd - goff_d(g);
        int gp1s = (g + 1) * (g + 1);
        int ub = goff_u(g) + d * gp1s;
        int chb = 32 * (3 - g) + lane;
        float acc = 0.f;
        for (int lp = 0; lp <= g; lp++) {
            int u2 = ub + lp * lp;
            int fb = foff(lp) + chb;
            int KL = klen(lp);
            for (int mm = 0; mm < 2 * lp + 1; mm++)
                acc = fmaf(Us[u2 + mm], fs[fb + mm * KL], acc);
        }
        outp[dd * 32 + lane] = acc;
    }
}

// ---------------------------------------------------------------------------
// K2: warp per edge. Radial via sin recurrence, S table cooperatively in smem,
//     gather unc_f[neighbor], multiply, atomicAdd into g_pool[center].
// ---------------------------------------------------------------------------
__global__ void __launch_bounds__(256) k_edge(
    const float* __restrict__ rr,
    const float* __restrict__ sh0, const float* __restrict__ sh1,
    const float* __restrict__ sh2, const float* __restrict__ sh3,
    const float* __restrict__ W0, const float* __restrict__ W1,
    const float* __restrict__ W2, const float* __restrict__ W3,
    const float* __restrict__ U0, const float* __restrict__ U1,
    const float* __restrict__ U2, const float* __restrict__ U3,
    const int* __restrict__ centers, const int* __restrict__ neighbors)
{
    __shared__ float Ws[2560];          // Wrad0..3 concat (offsets 0,1024,1792,2304)
    __shared__ float Us[526];           // U0..3 concat
    __shared__ float4 seS[8][40];       // per-warp S table (padded [dd][lp])
    __shared__ float  shS[8][16];       // per-warp sh values

    const int t = threadIdx.x;
    for (int i = t; i < 1024; i += 256) Ws[i]        = W0[i];
    for (int i = t; i < 768;  i += 256) Ws[1024 + i] = W1[i];
    for (int i = t; i < 512;  i += 256) Ws[1792 + i] = W2[i];
    for (int i = t; i < 256;  i += 256) Ws[2304 + i] = W3[i];
    if (t == 0) Us[0] = U0[0];
    for (int i = t; i < 12;  i += 256) Us[1  + i] = U1[i];
    for (int i = t; i < 81;  i += 256) Us[13 + i] = U2[i];
    for (int i = t; i < 432; i += 256) Us[94 + i] = U3[i];
    __syncthreads();

    const int w = t >> 5, lane = t & 31;
    const int e = blockIdx.x * 8 + w;
    if (e >= NE) return;

    // radial basis via Chebyshev sin recurrence: sin((n+1)x) = 2cos(x)sin(nx) - sin((n-1)x)
    const float rv = __ldg(rr + e);
    float s, c;
    sincosf(rv * 0.62831853071795864769f, &s, &c);   // theta = pi*r/5; r in [0.5,5] so no clipping needed
    const float scale = 0.5f * (c + 1.f) / (rv + 1e-6f);
    float rb[8];
    {
        float sp = 0.f, sc = s;
        rb[0] = sc * scale;
        #pragma unroll
        for (int i = 1; i < 8; i++) { float sn = 2.f * c * sc - sp; sp = sc; sc = sn; rb[i] = sc * scale; }
    }

    // radial values per lane: R[cmb], cmb = g*(g+1)/2 + lp, at channel 32*(3-g)+lane
    float R[10];
    #pragma unroll
    for (int g = 0; g < 4; g++) {
        const int ch = 32 * (3 - g) + lane;
        #pragma unroll
        for (int lp = 0; lp <= g; lp++) {
            const int wo = (lp == 0) ? 0 : (lp == 1) ? 1024 : (lp == 2) ? 1792 : 2304;
            const int KL = 32 * (4 - lp);
            float acc = 0.f;
            #pragma unroll
            for (int i = 0; i < 8; i++)
                acc = fmaf(rb[i], Ws[wo + i * KL + ch], acc);
            R[g * (g + 1) / 2 + lp] = acc;
        }
    }

    // sh values to smem (16 per edge)
    if (lane < 16) {
        float v;
        if      (lane == 0) v = __ldg(sh0 + e);
        else if (lane < 4)  v = __ldg(sh1 + e * 3 + (lane - 1));
        else if (lane < 9)  v = __ldg(sh2 + e * 5 + (lane - 4));
        else                v = __ldg(sh3 + e * 7 + (lane - 9));
        shS[w][lane] = v;
    }
    __syncwarp();

    // Phase A: cooperative S table.  S[dd][lp] = sum_mm U_g[d][lp^2+mm]*sh_lp[mm]
    {
        float* se = (float*)&seS[w][0];
        #pragma unroll
        for (int i = 0; i < 5; i++) {
            int slot = lane + 32 * i;         // 160 slots = 40 dd x 4 lp
            int dd = slot >> 2, lp = slot & 3;
            int g = dd2g(dd);
            float v = 0.f;
            if (lp <= g) {
                int d = dd - goff_d(g);
                int ub = goff_u(g) + d * (g + 1) * (g + 1) + lp * lp;
                for (int mm = 0; mm < 2 * lp + 1; mm++)
                    v = fmaf(Us[ub + mm], shS[w][lp * lp + mm], v);
            }
            se[slot] = v;
        }
    }
    __syncwarp();

    // Phase B: message + scatter
    const int nbr = __ldg(neighbors + e);
    const int ctr = __ldg(centers + e);
    const float* uf = g_uncf + (size_t)nbr * 1280 + lane;
    float*       pl = g_pool + (size_t)ctr * 1280 + lane;
    #pragma unroll
    for (int dd = 0; dd < 40; dd++) {
        const int g = (dd == 0) ? 0 : (dd < 4) ? 1 : (dd < 13) ? 2 : 3;   // folded at unroll
        const int cb = g * (g + 1) / 2;
        float4 s4 = seS[w][dd];
        float unc = R[cb] * s4.x;
        if (g >= 1) unc = fmaf(R[cb + 1], s4.y, unc);
        if (g >= 2) unc = fmaf(R[cb + 2], s4.z, unc);
        if (g >= 3) unc = fmaf(R[cb + 3], s4.w, unc);
        float f = __ldg(uf + dd * 32);
        atomicAdd(pl + dd * 32, unc * f);
    }
}

// ---------------------------------------------------------------------------
// K3: per-atom couple + cat + linear + residual, write output
// ---------------------------------------------------------------------------
__global__ void __launch_bounds__(256) k_out(
    const float* __restrict__ f0, const float* __restrict__ f1,
    const float* __restrict__ f2, const float* __restrict__ f3,
    const float* __restrict__ U0, const float* __restrict__ U1,
    const float* __restrict__ U2, const float* __restrict__ U3,
    const float* __restrict__ Wl0, const float* __restrict__ Wl1,
    const float* __restrict__ Wl2, const float* __restrict__ Wl3,
    float* __restrict__ out)
{
    __shared__ float ps[1280];
    __shared__ float xs[960];    // 30 coupled m-rows x 32 (row offsets per g: 0,1,5,14)
    __shared__ float Us[526];
    const int n = blockIdx.x, t = threadIdx.x;
    for (int i = t; i < 1280; i += 256) ps[i] = g_pool[(size_t)n * 1280 + i];
    if (t == 0) Us[0] = U0[0];
    for (int i = t; i < 12;  i += 256) Us[1  + i] = U1[i];
    for (int i = t; i < 81;  i += 256) Us[13 + i] = U2[i];
    for (int i = t; i < 432; i += 256) Us[94 + i] = U3[i];
    __syncthreads();

    const int lane = t & 31, row = t >> 5;
    // couple: x_g[m][k] = sum_d U_g[d][m] * pool[g][d][k]
    #pragma unroll
    for (int i = 0; i < 4; i++) {
        int gm = row + 8 * i;
        if (gm < 30) {
            int g = (gm == 0) ? 0 : (gm < 5) ? 1 : (gm < 14) ? 2 : 3;
            int m = gm - ((g == 0) ? 0 : (g == 1) ? 1 : (g == 2) ? 5 : 14);
            int doff = goff_d(g);
            int gp1s = (g + 1) * (g + 1);
            int p3 = pow3g(g);
            int uo = goff_u(g) + m;
            float acc = 0.f;
            for (int d = 0; d < p3; d++)
                acc = fmaf(Us[uo + d * gp1s], ps[(doff + d) * 32 + lane], acc);
            xs[gm * 32 + lane] = acc;
        }
    }
    __syncthreads();

    // matmul: out[l][m][q] = feat + sum_kg cat[l][m][kg] * Wlin_l[kg][q]
    // 240 float4 outputs per atom: l0:32, l1:72, l2:80, l3:56
    if (t < 240) {
        int l, m, q4, K; const float* W; const float* F; size_t obase;
        if (t < 32)       { l = 0; K = 128; W = Wl0; F = f0; m = 0;            q4 = t;            obase = 0; }
        else if (t < 104) { l = 1; K = 96;  W = Wl1; F = f1; int u = t - 32;  m = u / 24; q4 = u % 24; obase = 1280000; }
        else if (t < 184) { l = 2; K = 64;  W = Wl2; F = f2; int u = t - 104; m = u / 16; q4 = u % 16; obase = 4160000; }
        else              { l = 3; K = 32;  W = Wl3; F = f3; int u = t - 184; m = u / 8;  q4 = u % 8;  obase = 7360000; }
        const int rows = 2 * l + 1;
        const int Kq = K >> 2;
        float4 acc = make_float4(0.f, 0.f, 0.f, 0.f);
        const int mrow = l * l + m;
        for (int j = 0; j < 4 - l; j++) {
            int g = l + j;
            int gm = ((g == 0) ? 0 : (g == 1) ? 1 : (g == 2) ? 5 : 14) + mrow;
            const float4* Wr = (const float4*)W + (size_t)(32 * j) * Kq + q4;
            #pragma unroll
            for (int k = 0; k < 32; k++) {
                float xv = xs[gm * 32 + k];
                float4 wv = __ldg(Wr + (size_t)k * Kq);
                acc.x = fmaf(xv, wv.x, acc.x);
                acc.y = fmaf(xv, wv.y, acc.y);
                acc.z = fmaf(xv, wv.z, acc.z);
                acc.w = fmaf(xv, wv.w, acc.w);
            }
        }
        size_t rel4 = ((size_t)n * rows + m) * Kq + q4;   // in float4 units
        float4 fv = __ldg((const float4*)F + rel4);
        float4 ov = make_float4(fv.x + acc.x, fv.y + acc.y, fv.z + acc.z, fv.w + acc.w);
        ((float4*)out)[obase / 4 + rel4] = ov;
    }
}

// ---------------------------------------------------------------------------
extern "C" void kernel_launch(void* const* d_in, const int* in_sizes, int n_in,
                              void* d_out, int out_size)
{
    (void)n_in; (void)out_size;
    const float *Rr, *SH[4], *FT[4], *WR[4], *UU[4], *WL[4];
    const int *CT, *NB;
    if (in_sizes[2] == 1280000) {
        // dict insertion order: r, then per-l {sh, feat, Wrad, U, Wlin}, centers, neighbors
        Rr = (const float*)d_in[0];
        for (int l = 0; l < 4; l++) {
            SH[l] = (const float*)d_in[1 + 5 * l];
            FT[l] = (const float*)d_in[2 + 5 * l];
            WR[l] = (const float*)d_in[3 + 5 * l];
            UU[l] = (const float*)d_in[4 + 5 * l];
            WL[l] = (const float*)d_in[5 + 5 * l];
        }
        CT = (const int*)d_in[21]; NB = (const int*)d_in[22];
    } else {
        // signature order: r, sh0..3, feat0..3, Wrad0..3, U0..3, Wlin0..3, centers, neighbors
        Rr = (const float*)d_in[0];
        for (int l = 0; l < 4; l++) {
            SH[l] = (const float*)d_in[1 + l];
            FT[l] = (const float*)d_in[5 + l];
            WR[l] = (const float*)d_in[9 + l];
            UU[l] = (const float*)d_in[13 + l];
            WL[l] = (const float*)d_in[17 + l];
        }
        CT = (const int*)d_in[21]; NB = (const int*)d_in[22];
    }

    void* pptr = nullptr;
    cudaGetSymbolAddress(&pptr, g_pool);
    cudaMemsetAsync(pptr, 0, sizeof(float) * (size_t)NA * 1280, 0);

    k_uncf<<<NA, 256>>>(FT[0], FT[1], FT[2], FT[3], UU[0], UU[1], UU[2], UU[3]);
    k_edge<<<NE / 8, 256>>>(Rr, SH[0], SH[1], SH[2], SH[3],
                            WR[0], WR[1], WR[2], WR[3],
                            UU[0], UU[1], UU[2], UU[3], CT, NB);
    k_out<<<NA, 256>>>(FT[0], FT[1], FT[2], FT[3],
                       UU[0], UU[1], UU[2], UU[3],
                       WL[0], WL[1], WL[2], WL[3], (float*)d_out);
}